// round 14
// baseline (speedup 1.0000x reference)
#include <cuda_runtime.h>
#include <cuda_bf16.h>
#include <cuda_fp16.h>
#include <math.h>
#include <stdint.h>

// ---------------- problem constants ----------------
#define NN_   8192
#define DIN_  83
#define H_    256
#define C_    34
#define TD_   16
#define NL_   2
#define KNN_  11
#define NSTEPS_ 10
#define NTILE 64
#define NCAND (NTILE * KNN_)            // 704 candidates per row

typedef __half hf;

// ---------------- scratch (device globals; no allocation allowed) ----------------
__device__ float g_h  [NN_ * H_];
__device__ float g_h2 [NN_ * H_];
__device__ float g_hn [NN_ * H_];
__device__ float g_agg[NN_ * H_];
__device__ float g_d1 [NN_ * H_];
__device__ int   g_nidx[NN_ * KNN_];
__device__ float g_nval[NN_ * KNN_];
__device__ float g_bnscale[H_];
__device__ float g_bnshift[H_];
__device__ float g_gatec[NL_ * H_];
__device__ float g_sdebias[NSTEPS_ * H_];
__device__ float g_cv[(size_t)NN_ * NCAND];       // topk candidate values (23 MB)
__device__ int   g_ci[(size_t)NN_ * NCAND];       // topk candidate indices (23 MB)

// fp16 split copies of activations ([M,256] row-major hi/lo)
__device__ hf g_h_hi [NN_ * H_],  g_h_lo [NN_ * H_];
__device__ hf g_h2_hi[NN_ * H_],  g_h2_lo[NN_ * H_];
__device__ hf g_hn_hi[NN_ * H_],  g_hn_lo[NN_ * H_];
__device__ hf g_ag_hi[NN_ * H_],  g_ag_lo[NN_ * H_];

// transposed+split weights, [N,256] K-major; 9 slots of 64K elems
#define WSLOT 65536
__device__ hf g_w_hi[9 * WSLOT];
__device__ hf g_w_lo[9 * WSLOT];

// ================= helpers =================
__device__ __forceinline__ uint32_t smem_u32(const void* p) {
    uint32_t a;
    asm("{ .reg .u64 t; cvta.to.shared.u64 t, %1; cvt.u32.u64 %0, t; }" : "=r"(a) : "l"(p));
    return a;
}
__device__ __forceinline__ void ldsm4(uint32_t* r, uint32_t addr) {
    asm volatile("ldmatrix.sync.aligned.m8n8.x4.shared.b16 {%0,%1,%2,%3}, [%4];"
                 : "=r"(r[0]), "=r"(r[1]), "=r"(r[2]), "=r"(r[3]) : "r"(addr));
}
__device__ __forceinline__ void mma16816(float* d, const uint32_t* a, uint32_t b0, uint32_t b1) {
    asm volatile("mma.sync.aligned.m16n8k16.row.col.f32.f16.f16.f32 "
                 "{%0,%1,%2,%3}, {%4,%5,%6,%7}, {%8,%9}, {%0,%1,%2,%3};"
                 : "+f"(d[0]), "+f"(d[1]), "+f"(d[2]), "+f"(d[3])
                 : "r"(a[0]), "r"(a[1]), "r"(a[2]), "r"(a[3]), "r"(b0), "r"(b1));
}
__device__ __forceinline__ float fast_tanh(float x) {
    float ax = fabsf(x);
    float t = __expf(-2.f * ax);
    float r = __fdividef(1.f - t, 1.f + t);
    return copysignf(r, x);
}
__device__ __forceinline__ float fast_sigmoid(float x) {
    return __fdividef(1.f, 1.f + __expf(-x));
}
__device__ __forceinline__ void split2(float y0, float y1, hf* hi, hf* lo) {
    hf h0 = __float2half_rn(y0);
    hf h1 = __float2half_rn(y1);
    __half2 hp; hp.x = h0; hp.y = h1;
    __half2 lp;
    lp.x = __float2half_rn(y0 - __half2float(h0));
    lp.y = __float2half_rn(y1 - __half2float(h1));
    *(__half2*)hi = hp;
    *(__half2*)lo = lp;
}
#define CP_ASYNC16(sa, gp) \
    asm volatile("cp.async.cg.shared.global [%0], [%1], 16;" :: "r"(sa), "l"(gp))
#define CP_COMMIT() asm volatile("cp.async.commit_group;" ::: "memory")
#define CP_WAIT(n)  asm volatile("cp.async.wait_group %0;" :: "n"(n) : "memory")

#define TILE_B   8192                    // 128 rows * 32 hf * 2B
#define BUF_B    (4 * TILE_B)            // Ah,Al,Bh,Bl
#define MG_SMEM  (128 * 133 * 4)         // 68096 B: max(load bufs 64K, cand staging)

// tid-strided tile loader for NT threads (NT = 256 or 512)
template<int NT>
__device__ __forceinline__ void cpa_tile(const hf* __restrict__ src, int r0, int k0,
                                         char* __restrict__ dst, int tid)
{
#pragma unroll
    for (int u = 0; u < 512 / NT; u++) {
        int i = tid + u * NT;                // 512 16B segs
        int row = i >> 2;                    // 0..127
        int seg = i & 3;
        const void* gp = src + (size_t)(r0 + row) * 256 + k0 + seg * 8;
        uint32_t off = (uint32_t)row * 64u + (uint32_t)((seg ^ ((row >> 1) & 3)) << 4);
        CP_ASYNC16(smem_u32(dst + off), gp);
    }
}

// ================= dense tensor-core split-fp16 GEMM (512 thr, 32x32 warp tile) =================
__global__ __launch_bounds__(512) void mma_gemm(
    const hf* __restrict__ Ahi, const hf* __restrict__ Alo,
    const hf* __restrict__ Bhi, const hf* __restrict__ Blo,
    float* __restrict__ C, int Ntot, int ep,
    const float* __restrict__ p1, const float* __restrict__ p2,
    const float* __restrict__ p3, float alpha,
    hf* __restrict__ Chi, hf* __restrict__ Clo)
{
    const int bn0 = blockIdx.x * 128;
    const int bm0 = blockIdx.y * 128;

    extern __shared__ char smem[];
    char* bufp[2] = {smem, smem + BUF_B};

    const int tid  = threadIdx.x;
    const int wid  = tid >> 5;
    const int lane = tid & 31;
    const int warp_m = wid & 3;                 // rows  [warp_m*32, +32)
    const int warp_n = wid >> 2;                // cols  [warp_n*32, +32)

    float acc[2][4][4];
#pragma unroll
    for (int i = 0; i < 2; i++)
#pragma unroll
        for (int j = 0; j < 4; j++)
#pragma unroll
            for (int q = 0; q < 4; q++) acc[i][j][q] = 0.f;

    const int lrow  = lane & 15;
    const int lhalf = lane >> 4;

    cpa_tile<512>(Ahi, bm0, 0, bufp[0] + 0 * TILE_B, tid);
    cpa_tile<512>(Alo, bm0, 0, bufp[0] + 1 * TILE_B, tid);
    cpa_tile<512>(Bhi, bn0, 0, bufp[0] + 2 * TILE_B, tid);
    cpa_tile<512>(Blo, bn0, 0, bufp[0] + 3 * TILE_B, tid);
    CP_COMMIT();

    int buf = 0;
    for (int chunk = 0; chunk < 8; chunk++) {
        if (chunk + 1 < 8) {
            const int k1 = (chunk + 1) * 32;
            char* nb = bufp[buf ^ 1];
            cpa_tile<512>(Ahi, bm0, k1, nb + 0 * TILE_B, tid);
            cpa_tile<512>(Alo, bm0, k1, nb + 1 * TILE_B, tid);
            cpa_tile<512>(Bhi, bn0, k1, nb + 2 * TILE_B, tid);
            cpa_tile<512>(Blo, bn0, k1, nb + 3 * TILE_B, tid);
            CP_COMMIT();
            CP_WAIT(1);
        } else {
            CP_WAIT(0);
        }
        __syncthreads();

        const uint32_t sAh_b = smem_u32(bufp[buf] + 0 * TILE_B);
        const uint32_t sAl_b = smem_u32(bufp[buf] + 1 * TILE_B);
        const uint32_t sBh_b = smem_u32(bufp[buf] + 2 * TILE_B);
        const uint32_t sBl_b = smem_u32(bufp[buf] + 3 * TILE_B);

#pragma unroll
        for (int kk = 0; kk < 2; kk++) {
            const int segq = kk * 2 + lhalf;

            uint32_t aH[2][4], aL[2][4], bH[2][4], bL[2][4];
#pragma unroll
            for (int mt = 0; mt < 2; mt++) {
                int row = warp_m * 32 + mt * 16 + lrow;
                uint32_t off = (uint32_t)row * 64u + (uint32_t)((segq ^ ((row >> 1) & 3)) << 4);
                ldsm4(aH[mt], sAh_b + off);
                ldsm4(aL[mt], sAl_b + off);
            }
#pragma unroll
            for (int gg = 0; gg < 2; gg++) {
                int row = warp_n * 32 + gg * 16 + lrow;
                uint32_t off = (uint32_t)row * 64u + (uint32_t)((segq ^ ((row >> 1) & 3)) << 4);
                ldsm4(bH[gg], sBh_b + off);
                ldsm4(bL[gg], sBl_b + off);
            }

#define DO_TERM(Af, Bf)                                                        \
            _Pragma("unroll")                                                  \
            for (int mt = 0; mt < 2; mt++)                                     \
                _Pragma("unroll")                                              \
                for (int gg = 0; gg < 2; gg++) {                               \
                    mma16816(acc[mt][2 * gg + 0], Af[mt], Bf[gg][0], Bf[gg][2]); \
                    mma16816(acc[mt][2 * gg + 1], Af[mt], Bf[gg][1], Bf[gg][3]); \
                }
            DO_TERM(aH, bH)
            DO_TERM(aH, bL)
            DO_TERM(aL, bH)
#undef DO_TERM
        }
        __syncthreads();
        buf ^= 1;
    }

    auto epi = [&](float z, int gr, int gc) -> float {
        if (ep == 0) return z;
        if (ep == 1) return fmaxf(z + p1[gc], 0.f);
        if (ep == 2) return fmaxf(z + p1[gc], 0.f) * p2[gc] + p3[gc];
        if (ep == 3) return z + p1[gc];
        if (ep == 4) {
            float g = fast_sigmoid(z + p1[gc]);
            float a = p2[(size_t)gr * Ntot + gc];
            float hh = p3[(size_t)gr * Ntot + gc];
            return fmaxf(g * a + (1.f - g) * hh, 0.f);
        }
        if (ep == 5) return fast_tanh(z + p1[gc]);
        return p2[(size_t)gr * Ntot + gc] + fast_tanh(z + p1[gc]) * alpha;  // 6
    };

#pragma unroll
    for (int mt = 0; mt < 2; mt++) {
#pragma unroll
        for (int half = 0; half < 2; half++) {
            int gr = bm0 + warp_m * 32 + mt * 16 + (lane >> 2) + half * 8;
#pragma unroll
            for (int nt = 0; nt < 4; nt++) {
                int gc = bn0 + warp_n * 32 + nt * 8 + (lane & 3) * 2;
                float y0 = epi(acc[mt][nt][half * 2 + 0], gr, gc);
                float y1 = epi(acc[mt][nt][half * 2 + 1], gr, gc + 1);
                if (C) {
                    float2 o; o.x = y0; o.y = y1;
                    *(float2*)(C + (size_t)gr * Ntot + gc) = o;
                }
                if (Chi) {
                    split2(y0, y1, Chi + (size_t)gr * 256 + gc, Clo + (size_t)gr * 256 + gc);
                }
            }
        }
    }
}

// ================= sim GEMM + candidate extraction (256 thr, 32x64 warp tile) =================
__global__ __launch_bounds__(256, 2) void sim_cand(
    const hf* __restrict__ Ahi, const hf* __restrict__ Alo)
{
    const int bn0 = blockIdx.x * 128;
    const int bm0 = blockIdx.y * 128;
    if (bn0 > bm0) return;                      // symmetric: lower triangle only

    extern __shared__ char smem[];
    char* bufp[2] = {smem, smem + BUF_B};

    const int tid  = threadIdx.x;
    const int wid  = tid >> 5;
    const int lane = tid & 31;
    const int warp_m = wid & 3;                 // rows  [warp_m*32, +32)
    const int warp_n = wid >> 2;                // cols  [warp_n*64, +64)

    float acc[2][8][4];
#pragma unroll
    for (int i = 0; i < 2; i++)
#pragma unroll
        for (int j = 0; j < 8; j++)
#pragma unroll
            for (int q = 0; q < 4; q++) acc[i][j][q] = 0.f;

    const int lrow  = lane & 15;
    const int lhalf = lane >> 4;

    cpa_tile<256>(Ahi, bm0, 0, bufp[0] + 0 * TILE_B, tid);
    cpa_tile<256>(Alo, bm0, 0, bufp[0] + 1 * TILE_B, tid);
    cpa_tile<256>(Ahi, bn0, 0, bufp[0] + 2 * TILE_B, tid);
    cpa_tile<256>(Alo, bn0, 0, bufp[0] + 3 * TILE_B, tid);
    CP_COMMIT();

    int buf = 0;
    for (int chunk = 0; chunk < 8; chunk++) {
        if (chunk + 1 < 8) {
            const int k1 = (chunk + 1) * 32;
            char* nb = bufp[buf ^ 1];
            cpa_tile<256>(Ahi, bm0, k1, nb + 0 * TILE_B, tid);
            cpa_tile<256>(Alo, bm0, k1, nb + 1 * TILE_B, tid);
            cpa_tile<256>(Ahi, bn0, k1, nb + 2 * TILE_B, tid);
            cpa_tile<256>(Alo, bn0, k1, nb + 3 * TILE_B, tid);
            CP_COMMIT();
            CP_WAIT(1);
        } else {
            CP_WAIT(0);
        }
        __syncthreads();

        const uint32_t sAh_b = smem_u32(bufp[buf] + 0 * TILE_B);
        const uint32_t sAl_b = smem_u32(bufp[buf] + 1 * TILE_B);
        const uint32_t sBh_b = smem_u32(bufp[buf] + 2 * TILE_B);
        const uint32_t sBl_b = smem_u32(bufp[buf] + 3 * TILE_B);

#pragma unroll
        for (int kk = 0; kk < 2; kk++) {
            const int segq = kk * 2 + lhalf;

            uint32_t aH[2][4], aL[2][4], bH[4][4], bL[4][4];
#pragma unroll
            for (int mt = 0; mt < 2; mt++) {
                int row = warp_m * 32 + mt * 16 + lrow;
                uint32_t off = (uint32_t)row * 64u + (uint32_t)((segq ^ ((row >> 1) & 3)) << 4);
                ldsm4(aH[mt], sAh_b + off);
                ldsm4(aL[mt], sAl_b + off);
            }
#pragma unroll
            for (int gg = 0; gg < 4; gg++) {
                int row = warp_n * 64 + gg * 16 + lrow;
                uint32_t off = (uint32_t)row * 64u + (uint32_t)((segq ^ ((row >> 1) & 3)) << 4);
                ldsm4(bH[gg], sBh_b + off);
                ldsm4(bL[gg], sBl_b + off);
            }

#define DO_TERM(Af, Bf)                                                        \
            _Pragma("unroll")                                                  \
            for (int mt = 0; mt < 2; mt++)                                     \
                _Pragma("unroll")                                              \
                for (int gg = 0; gg < 4; gg++) {                               \
                    mma16816(acc[mt][2 * gg + 0], Af[mt], Bf[gg][0], Bf[gg][2]); \
                    mma16816(acc[mt][2 * gg + 1], Af[mt], Bf[gg][1], Bf[gg][3]); \
                }
            DO_TERM(aH, bH)
            DO_TERM(aH, bL)
            DO_TERM(aL, bH)
#undef DO_TERM
        }
        __syncthreads();
        buf ^= 1;
    }

    // ---- stage full 128x128 tile, pitch 133 (conflict-free row & col scans) ----
    float* ts = (float*)smem;
#pragma unroll
    for (int mt = 0; mt < 2; mt++)
#pragma unroll
        for (int half = 0; half < 2; half++) {
            int lr = warp_m * 32 + mt * 16 + (lane >> 2) + half * 8;
#pragma unroll
            for (int nt = 0; nt < 8; nt++) {
                int lc = warp_n * 64 + nt * 8 + (lane & 3) * 2;
                ts[lr * 133 + lc]     = acc[mt][nt][half * 2 + 0];
                ts[lr * 133 + lc + 1] = acc[mt][nt][half * 2 + 1];
            }
        }
    __syncthreads();

    float lv[KNN_]; int li[KNN_];
    if (tid < 128) {
        // direct: row bm0+tid, cols bn0..+127
        int r = tid;
#pragma unroll
        for (int q = 0; q < KNN_; q++) { lv[q] = -INFINITY; li[q] = 0x7fffffff; }
        for (int c = 0; c < 128; c++) {
            float v = ts[r * 133 + c];
            if (v > lv[KNN_ - 1]) {
                int p = KNN_ - 1;
                while (p > 0 && v > lv[p - 1]) { lv[p] = lv[p - 1]; li[p] = li[p - 1]; p--; }
                lv[p] = v; li[p] = bn0 + c;
            }
        }
        size_t base = (size_t)(bm0 + r) * NCAND + (size_t)(bn0 >> 7) * KNN_;
#pragma unroll
        for (int q = 0; q < KNN_; q++) { g_cv[base + q] = lv[q]; g_ci[base + q] = li[q]; }
    } else if (bm0 != bn0) {
        // mirror: row bn0+c, cols bm0..+127 (column scan of staged tile)
        int c = tid - 128;
#pragma unroll
        for (int q = 0; q < KNN_; q++) { lv[q] = -INFINITY; li[q] = 0x7fffffff; }
        for (int r = 0; r < 128; r++) {
            float v = ts[r * 133 + c];
            if (v > lv[KNN_ - 1]) {
                int p = KNN_ - 1;
                while (p > 0 && v > lv[p - 1]) { lv[p] = lv[p - 1]; li[p] = li[p - 1]; p--; }
                lv[p] = v; li[p] = bm0 + r;
            }
        }
        size_t base = (size_t)(bn0 + c) * NCAND + (size_t)(bm0 >> 7) * KNN_;
#pragma unroll
        for (int q = 0; q < KNN_; q++) { g_cv[base + q] = lv[q]; g_ci[base + q] = li[q]; }
    }
}

// ================= fused persistent SDE kernel (512 thr; h in registers; 64-k W ring) =================
// 10 steps x 3 layers as a flat stream of 120 64-k weight chunks, 1 chunk prefetch ahead
// (cross-layer: no cold pipeline restarts). u splits resident in smem; h in registers.
#define SDE_UH   0                       // hf, swizzled    32 KB
#define SDE_UL   32768                   // hf, swizzled    32 KB
#define SDE_W    65536                   // ring: 2 x 64 KB (hi sub0|hi sub1|lo sub0|lo sub1)
#define SDE_SMEM 196608

// load one 64-k chunk half (hi or lo) = 32 KB as two 32-k sub-chunks
__device__ __forceinline__ void sde_wchunk64(const hf* __restrict__ W, int k0,
                                             char* __restrict__ dst, int tid)
{
#pragma unroll
    for (int u = 0; u < 4; u++) {
        int i = tid + u * 512;               // 2048 segs: 256 rows x 8
        int row = i >> 3, s = i & 7;
        const void* gp = W + (size_t)row * 256 + k0 + s * 8;
        uint32_t off = (uint32_t)(s >> 2) * 16384u + (uint32_t)row * 64u
                     + ((uint32_t)((s & 3) ^ ((row >> 1) & 3)) << 4);
        CP_ASYNC16(smem_u32(dst + off), gp);
    }
}

__global__ __launch_bounds__(512) void sde_fused(
    const hf* __restrict__ W1h, const hf* __restrict__ W1l,
    const hf* __restrict__ W2h, const hf* __restrict__ W2l,
    const hf* __restrict__ W3h, const hf* __restrict__ W3l,
    const float* __restrict__ sdeb, const float* __restrict__ b2,
    const float* __restrict__ b3,
    const float* __restrict__ hin,
    hf* __restrict__ hhi_g, hf* __restrict__ hlo_g)
{
    extern __shared__ char smem[];
    char* sUh = smem + SDE_UH;
    char* sUl = smem + SDE_UL;
    char* sW  = smem + SDE_W;

    const int tid  = threadIdx.x;
    const int wid  = tid >> 5;
    const int lane = tid & 31;
    const int warp_m = wid & 3;              // 4 warps over m (16 rows each)
    const int warp_n = wid >> 2;             // 4 warps over n (64 cols each)
    const int r0 = blockIdx.x * 64;
    const int lrow  = lane & 15;
    const int lhalf = lane >> 4;

    // u-split initial load (swizzled chunk layout), group 0
#pragma unroll
    for (int u = 0; u < 4; u++) {
        int i = tid + u * 512;               // 2048 segs: 64 rows x 32
        int row = i >> 5, s32 = i & 31;
        int chunk = s32 >> 2, seg = s32 & 3;
        uint32_t off = (uint32_t)chunk * 4096u + (uint32_t)row * 64u
                     + (uint32_t)((seg ^ ((row >> 1) & 3)) << 4);
        CP_ASYNC16(smem_u32(sUh + off), (const void*)(hhi_g + (size_t)(r0 + row) * 256 + s32 * 8));
        CP_ASYNC16(smem_u32(sUl + off), (const void*)(hlo_g + (size_t)(r0 + row) * 256 + s32 * 8));
    }
    CP_COMMIT();

    // h state into registers (exactly the elements this thread's epilogue owns)
    float hreg[2][8][2];
#pragma unroll
    for (int half = 0; half < 2; half++) {
        int lr = warp_m * 16 + (lane >> 2) + half * 8;
#pragma unroll
        for (int nt = 0; nt < 8; nt++) {
            int gc = warp_n * 64 + nt * 8 + (lane & 3) * 2;
            float2 v = *(const float2*)(hin + (size_t)(r0 + lr) * 256 + gc);
            hreg[half][nt][0] = v.x;
            hreg[half][nt][1] = v.y;
        }
    }

    // weight pointer per chunk-instance
    const hf* Whs[3] = {W1h, W2h, W3h};
    const hf* Wls[3] = {W1l, W2l, W3l};

    // prefetch global chunk 0 (inst 0, kc 0), group 1
    sde_wchunk64(W1h, 0, sW, tid);
    sde_wchunk64(W1l, 0, sW + 32768, tid);
    CP_COMMIT();

#pragma unroll 1
    for (int inst = 0; inst < 3 * NSTEPS_; inst++) {
        const int layer = inst % 3;
        const int step  = inst / 3;
        const float* bias = (layer == 0) ? (sdeb + step * H_) : (layer == 1) ? b2 : b3;

        float acc[8][4];
#pragma unroll
        for (int j = 0; j < 8; j++)
#pragma unroll
            for (int q = 0; q < 4; q++) acc[j][q] = 0.f;

#pragma unroll 1
        for (int kc = 0; kc < 4; kc++) {
            const int g = inst * 4 + kc;
            if (g + 1 < 120) {
                const int g2 = g + 1;
                const int w2 = (g2 >> 2) % 3;
                char* nb = sW + ((g2 & 1) ? 65536 : 0);
                sde_wchunk64(Whs[w2], (g2 & 3) * 64, nb, tid);
                sde_wchunk64(Wls[w2], (g2 & 3) * 64, nb + 32768, tid);
                CP_COMMIT();
                CP_WAIT(1);
            } else {
                CP_WAIT(0);
            }
            __syncthreads();

            const uint32_t wb = smem_u32(sW + ((g & 1) ? 65536 : 0));
#pragma unroll
            for (int kk2 = 0; kk2 < 4; kk2++) {
                const int sub  = kk2 >> 1;
                const int segq = (kk2 & 1) * 2 + lhalf;
                const uint32_t sWh_b = wb + (uint32_t)sub * 16384u;
                const uint32_t sWl_b = wb + 32768u + (uint32_t)sub * 16384u;
                const uint32_t sAh_b = smem_u32(sUh) + (uint32_t)(kc * 2 + sub) * 4096u;
                const uint32_t sAl_b = smem_u32(sUl) + (uint32_t)(kc * 2 + sub) * 4096u;

                uint32_t aH[4], aL[4], bH[4][4], bL[4][4];
                {
                    int row = warp_m * 16 + lrow;
                    uint32_t off = (uint32_t)row * 64u
                                 + (uint32_t)((segq ^ ((row >> 1) & 3)) << 4);
                    ldsm4(aH, sAh_b + off);
                    ldsm4(aL, sAl_b + off);
                }
#pragma unroll
                for (int gg = 0; gg < 4; gg++) {
                    int row = warp_n * 64 + gg * 16 + lrow;
                    uint32_t off = (uint32_t)row * 64u
                                 + (uint32_t)((segq ^ ((row >> 1) & 3)) << 4);
                    ldsm4(bH[gg], sWh_b + off);
                    ldsm4(bL[gg], sWl_b + off);
                }
#define DO_TERM4(Af, Bf)                                                       \
                _Pragma("unroll")                                              \
                for (int gg = 0; gg < 4; gg++) {                               \
                    mma16816(acc[2 * gg + 0], Af, Bf[gg][0], Bf[gg][2]);       \
                    mma16816(acc[2 * gg + 1], Af, Bf[gg][1], Bf[gg][3]);       \
                }
                DO_TERM4(aH, bH)
                DO_TERM4(aH, bL)
                DO_TERM4(aL, bH)
#undef DO_TERM4
            }
            __syncthreads();
        }

        const bool lastL = (layer == 2);
        const bool fin = lastL && (step == NSTEPS_ - 1);
#pragma unroll
        for (int half = 0; half < 2; half++) {
            int lr = warp_m * 16 + (lane >> 2) + half * 8;
#pragma unroll
            for (int nt = 0; nt < 8; nt++) {
                int gc = warp_n * 64 + nt * 8 + (lane & 3) * 2;
                float y0 = fast_tanh(acc[nt][half * 2 + 0] + bias[gc]);
                float y1 = fast_tanh(acc[nt][half * 2 + 1] + bias[gc + 1]);
                if (lastL) {
                    y0 = hreg[half][nt][0] + y0 * 0.1f;
                    y1 = hreg[half][nt][1] + y1 * 0.1f;
                    if (!fin) {
                        hreg[half][nt][0] = y0;
                        hreg[half][nt][1] = y1;
                    }
                }
                if (fin) {
                    split2(y0, y1, hhi_g + (size_t)(r0 + lr) * 256 + gc,
                                   hlo_g + (size_t)(r0 + lr) * 256 + gc);
                } else {
                    int chunk = gc >> 5, k = gc & 31, seg = k >> 3;
                    uint32_t boff = (uint32_t)chunk * 4096u + (uint32_t)lr * 64u
                                  + (uint32_t)((seg ^ ((lr >> 1) & 3)) << 4)
                                  + (uint32_t)(k & 7) * 2u;
                    split2(y0, y1, (hf*)(sUh + boff), (hf*)(sUl + boff));
                }
            }
        }
        __syncthreads();
    }
}

// ================= SIMT fp32 GEMM (odd shapes: enc1 K=83, dec2 N=34) =================
#define BM 128
#define BN 128
#define BK 8

__global__ __launch_bounds__(256) void gemm_kernel(
    const float* __restrict__ A, const float* __restrict__ B, float* __restrict__ C,
    int M, int N, int K, int ldb, int ep,
    const float* __restrict__ p1, hf* __restrict__ Chi, hf* __restrict__ Clo)
{
    __shared__ float As[2][BK][BM + 4];
    __shared__ float Bs[2][BK][BN + 4];

    const int tid = threadIdx.x;
    const int tx  = tid & 15;
    const int ty  = tid >> 4;
    const int bn0 = blockIdx.x * BN;
    const int bm0 = blockIdx.y * BM;

    float acc[8][8];
#pragma unroll
    for (int i = 0; i < 8; i++)
#pragma unroll
        for (int j = 0; j < 8; j++) acc[i][j] = 0.f;

    const int aRow = tid >> 1;
    const int aK   = (tid & 1) * 4;
    const int bRow = tid >> 5;
    const int bN   = (tid & 31) * 4;

    float ra[4], rb[4];
    const int ktiles = (K + BK - 1) / BK;

#define LOAD_AB(kt) do {                                                       \
        int k0_ = (kt) * BK;                                                   \
        int gr_ = bm0 + aRow, gk_ = k0_ + aK;                                  \
        _Pragma("unroll")                                                      \
        for (int j_ = 0; j_ < 4; j_++)                                         \
            ra[j_] = (gr_ < M && gk_ + j_ < K) ? A[(size_t)gr_ * K + gk_ + j_] : 0.f; \
        int gk2_ = k0_ + bRow, gn_ = bn0 + bN;                                 \
        _Pragma("unroll")                                                      \
        for (int j_ = 0; j_ < 4; j_++)                                         \
            rb[j_] = (gk2_ < K && gn_ + j_ < N) ? B[(size_t)gk2_ * ldb + gn_ + j_] : 0.f; \
    } while (0)

#define STS_AB2(buf) do {                                                      \
        _Pragma("unroll")                                                      \
        for (int j_ = 0; j_ < 4; j_++) As[buf][aK + j_][aRow] = ra[j_];        \
        _Pragma("unroll")                                                      \
        for (int j_ = 0; j_ < 4; j_++) Bs[buf][bRow][bN + j_] = rb[j_];        \
    } while (0)

    LOAD_AB(0);
    STS_AB2(0);
    __syncthreads();

    int cur = 0;
    for (int kt = 0; kt < ktiles; kt++) {
        const int hasNext = (kt + 1 < ktiles);
        if (hasNext) LOAD_AB(kt + 1);
#pragma unroll
        for (int kk = 0; kk < BK; kk++) {
            const float* as = As[cur][kk];
            const float* bs = Bs[cur][kk];
            float4 A0 = *(const float4*)(as + ty * 4);
            float4 A1 = *(const float4*)(as + 64 + ty * 4);
            float4 B0 = *(const float4*)(bs + tx * 4);
            float4 B1 = *(const float4*)(bs + 64 + tx * 4);
            float av[8] = {A0.x, A0.y, A0.z, A0.w, A1.x, A1.y, A1.z, A1.w};
            float bv[8] = {B0.x, B0.y, B0.z, B0.w, B1.x, B1.y, B1.z, B1.w};
#pragma unroll
            for (int i = 0; i < 8; i++)
#pragma unroll
                for (int j = 0; j < 8; j++)
                    acc[i][j] = fmaf(av[i], bv[j], acc[i][j]);
        }
        if (hasNext) { STS_AB2(cur ^ 1); __syncthreads(); cur ^= 1; }
    }

#pragma unroll
    for (int i = 0; i < 8; i++) {
        int gr = bm0 + ((i < 4) ? (ty * 4 + i) : (64 + ty * 4 + (i - 4)));
        if (gr >= M) continue;
#pragma unroll
        for (int j = 0; j < 8; j++) {
            int gc = bn0 + ((j < 4) ? (tx * 4 + j) : (64 + tx * 4 + (j - 4)));
            if (gc >= N) continue;
            float z = acc[i][j];
            float y;
            if (ep == 1) y = fmaxf(z + p1[gc], 0.f);
            else if (ep == 3) y = z + p1[gc];
            else y = z;
            if (C) C[(size_t)gr * N + gc] = y;
            if (Chi) {
                hf hb = __float2half_rn(y);
                Chi[(size_t)gr * 256 + gc] = hb;
                Clo[(size_t)gr * 256 + gc] = __float2half_rn(y - __half2float(hb));
            }
        }
    }
}

// ---------------- row-normalize h -> hn (+ fp16 split) ----------------
__global__ void rownorm_kernel()
{
    int row = blockIdx.x;
    int tid = threadIdx.x;                   // 256 == H_
    float v = g_h[row * H_ + tid];
    float s = v * v;
#pragma unroll
    for (int o = 16; o > 0; o >>= 1) s += __shfl_xor_sync(0xffffffff, s, o);
    __shared__ float ws[8];
    if ((tid & 31) == 0) ws[tid >> 5] = s;
    __syncthreads();
    if (tid < 8) {
        float t = ws[tid];
#pragma unroll
        for (int o = 4; o > 0; o >>= 1) t += __shfl_xor_sync(0xff, t, o);
        if (tid == 0) ws[0] = t;
    }
    __syncthreads();
    float denom = fmaxf(sqrtf(ws[0]), 1e-12f);
    float y = v / denom;
    g_hn[row * H_ + tid] = y;
    hf hb = __float2half_rn(y);
    g_hn_hi[row * H_ + tid] = hb;
    g_hn_lo[row * H_ + tid] = __float2half_rn(y - __half2float(hb));
}

// ---------------- top-k over per-tile candidates + adjacency normalize ----------------
__global__ void topk_kernel()
{
    const int row = blockIdx.x;
    const int tid = threadIdx.x;             // 256
    const float* cv = g_cv + (size_t)row * NCAND;
    const int*   ci = g_ci + (size_t)row * NCAND;

    float lv[KNN_];
    int   li[KNN_];
#pragma unroll
    for (int r = 0; r < KNN_; r++) { lv[r] = -INFINITY; li[r] = 0x7fffffff; }

    for (int j = tid; j < NCAND; j += 256) {
        float v = cv[j];
        int ii = ci[j];
        if (v > lv[KNN_ - 1] || (v == lv[KNN_ - 1] && ii < li[KNN_ - 1])) {
            int p = KNN_ - 1;
            while (p > 0 && (v > lv[p - 1] || (v == lv[p - 1] && ii < li[p - 1]))) {
                lv[p] = lv[p - 1]; li[p] = li[p - 1]; p--;
            }
            lv[p] = v; li[p] = ii;
        }
    }

    __shared__ float sv[256 * KNN_];
    __shared__ int   si[256 * KNN_];
#pragma unroll
    for (int r = 0; r < KNN_; r++) { sv[tid * KNN_ + r] = lv[r]; si[tid * KNN_ + r] = li[r]; }
    __syncthreads();

    __shared__ float rv[256];
    __shared__ int   ri[256];
    __shared__ int   rp[256];
    __shared__ float outv[KNN_];
    __shared__ int   outi[KNN_];

    const int TOT = 256 * KNN_;
    for (int r = 0; r < KNN_; r++) {
        float bv = -INFINITY; int bi = 0x7fffffff; int bp = -1;
        for (int t = tid; t < TOT; t += 256) {
            float v = sv[t]; int ii = si[t];
            if (v > bv || (v == bv && ii < bi)) { bv = v; bi = ii; bp = t; }
        }
        rv[tid] = bv; ri[tid] = bi; rp[tid] = bp;
        __syncthreads();
        for (int s = 128; s > 0; s >>= 1) {
            if (tid < s) {
                float v2 = rv[tid + s]; int i2 = ri[tid + s];
                if (v2 > rv[tid] || (v2 == rv[tid] && i2 < ri[tid])) {
                    rv[tid] = v2; ri[tid] = i2; rp[tid] = rp[tid + s];
                }
            }
            __syncthreads();
        }
        if (tid == 0) {
            outv[r] = rv[0]; outi[r] = ri[0];
            sv[rp[0]] = -INFINITY;
            si[rp[0]] = 0x7fffffff;
        }
        __syncthreads();
    }

    if (tid == 0) {
        float s = 0.f;
#pragma unroll
        for (int r = 0; r < KNN_; r++) s += outv[r];
        float inv = 1.f / fmaxf(s, 1.f);
#pragma unroll
        for (int r = 0; r < KNN_; r++) {
            g_nidx[row * KNN_ + r] = outi[r];
            g_nval[row * KNN_ + r] = outv[r] * inv;
        }
    }
}

// ---------------- sparse aggregation (+ fp16 split) ----------------
__global__ void agg_kernel()
{
    int row = blockIdx.x;
    int tid = threadIdx.x;                  // 256 == H_
    float acc = 0.f;
#pragma unroll
    for (int r = 0; r < KNN_; r++) {
        float w = g_nval[row * KNN_ + r];
        int   n = g_nidx[row * KNN_ + r];
        acc += w * g_h2[(size_t)n * H_ + tid];
    }
    g_agg[row * H_ + tid] = acc;
    hf hb = __float2half_rn(acc);
    g_ag_hi[row * H_ + tid] = hb;
    g_ag_lo[row * H_ + tid] = __float2half_rn(acc - __half2float(hb));
}

// ---------------- all weight transposes+splits in ONE launch ----------------
__global__ void wsplit_all(
    const float* w0, const float* w1, const float* w2, const float* w3,
    const float* w4, const float* w5, const float* w6, const float* w7,
    const float* w8, hf* __restrict__ hi_base, hf* __restrict__ lo_base)
{
    const int slot = blockIdx.z;
    const float* W = (slot == 0) ? w0 : (slot == 1) ? w1 : (slot == 2) ? w2 :
                     (slot == 3) ? w3 : (slot == 4) ? w4 : (slot == 5) ? w5 :
                     (slot == 6) ? w6 : (slot == 7) ? w7 : w8;
    const int N = (slot == 8) ? 128 : 256;
    hf* hi = hi_base + (size_t)slot * WSLOT;
    hf* lo = lo_base + (size_t)slot * WSLOT;

    __shared__ float t[32][33];
    const int n0 = blockIdx.x * 32;
    if (n0 >= N) return;
    const int k0 = blockIdx.y * 32;
    const int tx = threadIdx.x;
    const int ty = threadIdx.y;
#pragma unroll
    for (int i = ty; i < 32; i += 8)
        t[i][tx] = W[(size_t)(k0 + i) * N + n0 + tx];
    __syncthreads();
#pragma unroll
    for (int i = ty; i < 32; i += 8) {
        float v = t[tx][i];
        hf hb = __float2half_rn(v);
        hi[(size_t)(n0 + i) * 256 + k0 + tx] = hb;
        lo[(size_t)(n0 + i) * 256 + k0 + tx] = __float2half_rn(v - __half2float(hb));
    }
}

// ---------------- tiny precompute ----------------
__global__ void precompute_kernel(const float* __restrict__ bn_g, const float* __restrict__ bn_b,
                                  const float* __restrict__ bn_m, const float* __restrict__ bn_v,
                                  const float* __restrict__ t_w1, const float* __restrict__ t_b1,
                                  const float* __restrict__ t_w2, const float* __restrict__ t_b2,
                                  const float* __restrict__ gate_w, const float* __restrict__ gate_b,
                                  const float* __restrict__ sde_w1, const float* __restrict__ sde_b1)
{
    int b = blockIdx.x;
    int j = threadIdx.x;
    if (b == 0) {
        float s = bn_g[j] * rsqrtf(bn_v[j] + 1e-5f);
        g_bnscale[j] = s;
        g_bnshift[j] = bn_b[j] - bn_m[j] * s;
    } else if (b <= NL_) {
        int l = b - 1;
        float t = 0.5f * (float)l;
        __shared__ float te[TD_];
        __shared__ float te2[H_];
        if (j < TD_) te[j] = fmaxf(t * t_w1[l * TD_ + j] + t_b1[l * TD_ + j], 0.f);
        __syncthreads();
        float acc = t_b2[l * H_ + j];
#pragma unroll
        for (int k = 0; k < TD_; k++) acc += te[k] * t_w2[l * TD_ * H_ + k * H_ + j];
        te2[j] = acc;
        __syncthreads();
        float c = gate_b[l * H_ + j];
        const float* W = gate_w + (size_t)l * 2 * H_ * H_ + (size_t)H_ * H_;
        for (int k = 0; k < H_; k++) c += te2[k] * W[k * H_ + j];
        g_gatec[l * H_ + j] = c;
    } else {
        int s = b - 1 - NL_;
        float ts = (float)s * 0.1f;
        g_sdebias[s * H_ + j] = sde_b1[j] + ts * sde_w1[H_ * H_ + j];
    }
}

// ---------------- host ----------------
static inline void launch_mma(const hf* Ahi, const hf* Alo, const hf* Bhi, const hf* Blo,
                              float* C, int Ntot, int ep,
                              const float* p1 = nullptr, const float* p2 = nullptr,
                              const float* p3 = nullptr, float alpha = 0.f,
                              hf* Chi = nullptr, hf* Clo = nullptr)
{
    dim3 grid(Ntot / 128, NN_ / 128);
    mma_gemm<<<grid, 512, MG_SMEM>>>(Ahi, Alo, Bhi, Blo, C, Ntot, ep,
                                     p1, p2, p3, alpha, Chi, Clo);
}

extern "C" void kernel_launch(void* const* d_in, const int* in_sizes, int n_in,
                              void* d_out, int out_size)
{
    const float* x       = (const float*)d_in[0];
    const float* enc_w1  = (const float*)d_in[1];
    const float* enc_b1  = (const float*)d_in[2];
    const float* enc_w2  = (const float*)d_in[3];
    const float* enc_b2  = (const float*)d_in[4];
    const float* bn_g    = (const float*)d_in[5];
    const float* bn_b    = (const float*)d_in[6];
    const float* bn_m    = (const float*)d_in[7];
    const float* bn_v    = (const float*)d_in[8];
    const float* node_w  = (const float*)d_in[9];
    const float* node_b  = (const float*)d_in[10];
    const float* t_w1    = (const float*)d_in[11];
    const float* t_b1    = (const float*)d_in[12];
    const float* t_w2    = (const float*)d_in[13];
    const float* t_b2    = (const float*)d_in[14];
    const float* gate_w  = (const float*)d_in[15];
    const float* gate_b  = (const float*)d_in[16];
    const float* sde_w1  = (const float*)d_in[17];
    const float* sde_b1  = (const float*)d_in[18];
    const float* sde_w2  = (const float*)d_in[19];
    const float* sde_b2  = (const float*)d_in[20];
    const float* sde_w3  = (const float*)d_in[21];
    const float* sde_b3  = (const float*)d_in[22];
    const float* dec_w1  = (const float*)d_in[23];
    const float* dec_b1  = (const float*)d_in[24];
    const float* dec_w2  = (const float*)d_in[25];
    const float* dec_b2  = (const float*)d_in[26];
    float* out = (float*)d_out;

    cudaFuncSetAttribute(mma_gemm, cudaFuncAttributeMaxDynamicSharedMemorySize, MG_SMEM);
    cudaFuncSetAttribute(sim_cand, cudaFuncAttributeMaxDynamicSharedMemorySize, MG_SMEM);
    cudaFuncSetAttribute(sde_fused, cudaFuncAttributeMaxDynamicSharedMemorySize, SDE_SMEM);

    float *h, *h2, *hn, *agg, *d1, *bns, *bnsh, *gatec, *sdeb;
    hf *hhi, *hlo, *h2hi, *h2lo, *hnhi, *hnlo, *aghi, *aglo, *whi, *wlo;
    cudaGetSymbolAddress((void**)&h,     g_h);
    cudaGetSymbolAddress((void**)&h2,    g_h2);
    cudaGetSymbolAddress((void**)&hn,    g_hn);
    cudaGetSymbolAddress((void**)&agg,   g_agg);
    cudaGetSymbolAddress((void**)&d1,    g_d1);
    cudaGetSymbolAddress((void**)&bns,   g_bnscale);
    cudaGetSymbolAddress((void**)&bnsh,  g_bnshift);
    cudaGetSymbolAddress((void**)&gatec, g_gatec);
    cudaGetSymbolAddress((void**)&sdeb,  g_sdebias);
    cudaGetSymbolAddress((void**)&hhi,  g_h_hi);  cudaGetSymbolAddress((void**)&hlo,  g_h_lo);
    cudaGetSymbolAddress((void**)&h2hi, g_h2_hi); cudaGetSymbolAddress((void**)&h2lo, g_h2_lo);
    cudaGetSymbolAddress((void**)&hnhi, g_hn_hi); cudaGetSymbolAddress((void**)&hnlo, g_hn_lo);
    cudaGetSymbolAddress((void**)&aghi, g_ag_hi); cudaGetSymbolAddress((void**)&aglo, g_ag_lo);
    cudaGetSymbolAddress((void**)&whi, g_w_hi);   cudaGetSymbolAddress((void**)&wlo, g_w_lo);

    // (1) precompute
    precompute_kernel<<<1 + NL_ + NSTEPS_, 256>>>(bn_g, bn_b, bn_m, bn_v,
                                                  t_w1, t_b1, t_w2, t_b2,
                                                  gate_w, gate_b, sde_w1, sde_b1);
    // (2) ALL weight splits in one launch
    {
        dim3 grid(8, 8, 9);
        wsplit_all<<<grid, dim3(32, 8)>>>(
            enc_w2, node_w, node_w + H_ * H_, gate_w, gate_w + 2 * H_ * H_,
            sde_w1, sde_w2, sde_w3, dec_w1, whi, wlo);
    }
    // (3) enc1 SIMT (K=83), splits only
    {
        dim3 grid((H_ + BN - 1) / BN, (NN_ + BM - 1) / BM);
        gemm_kernel<<<grid, 256>>>(x, enc_w1, nullptr, NN_, H_, DIN_, H_, 1, enc_b1, h2hi, h2lo);
    }
    // (4) enc2 mma (dense, 512-thr config)
    launch_mma(h2hi, h2lo, whi + 0 * WSLOT, wlo + 0 * WSLOT, h, 256, /*ep=*/2,
               enc_b2, bns, bnsh, 0.f, hhi, hlo);
    // (5) rownorm
    rownorm_kernel<<<NN_, 256>>>();
    // (6) sim GEMM + fused candidate extraction (256-thr config; sim never hits DRAM)
    {
        dim3 grid(NN_ / 128, NN_ / 128);
        sim_cand<<<grid, 256, MG_SMEM>>>(hnhi, hnlo);
    }
    // (7) top-k over candidates
    topk_kernel<<<NN_, 256>>>();

    // temporal gated graph conv layers
    for (int l = 0; l < NL_; l++) {
        launch_mma(hhi, hlo, whi + (1 + l) * WSLOT, wlo + (1 + l) * WSLOT, h2, 256, /*ep=*/3,
                   node_b + (size_t)l * H_);
        agg_kernel<<<NN_, 256>>>();
        launch_mma(aghi, aglo, whi + (3 + l) * WSLOT, wlo + (3 + l) * WSLOT, h, 256, /*ep=*/4,
                   gatec + (size_t)l * H_, agg, h2, 0.f, hhi, hlo);
    }

    // SDE: fused persistent kernel (128 CTAs x 64 rows; h in regs; 64-k W ring)
    sde_fused<<<NN_ / 64, 512, SDE_SMEM>>>(
        whi + 5 * WSLOT, wlo + 5 * WSLOT,
        whi + 6 * WSLOT, wlo + 6 * WSLOT,
        whi + 7 * WSLOT, wlo + 7 * WSLOT,
        sdeb, sde_b2, sde_b3, h, hhi, hlo);

    // decoder: dec1 tensor (N=128), dec2 SIMT (K=128, N=34)
    launch_mma(hhi, hlo, whi + 8 * WSLOT, wlo + 8 * WSLOT, d1, 128, /*ep=*/1, dec_b1);
    {
        dim3 grid((C_ + BN - 1) / BN, (NN_ + BM - 1) / BM);
        gemm_kernel<<<grid, 256>>>(d1, dec_w2, out, NN_, C_, H_ / 2, C_, 3, dec_b2, nullptr, nullptr);
    }
}

// round 15
// speedup vs baseline: 1.0202x; 1.0202x over previous
#include <cuda_runtime.h>
#include <cuda_bf16.h>
#include <cuda_fp16.h>
#include <math.h>
#include <stdint.h>

// ---------------- problem constants ----------------
#define NN_   8192
#define DIN_  83
#define H_    256
#define C_    34
#define TD_   16
#define NL_   2
#define KNN_  11
#define NSTEPS_ 10
#define NTILE 64
#define NCAND (NTILE * KNN_)            // 704 candidates per row

typedef __half hf;

// ---------------- scratch (device globals; no allocation allowed) ----------------
__device__ float g_h  [NN_ * H_];
__device__ float g_h2 [NN_ * H_];
__device__ float g_agg[NN_ * H_];
__device__ float g_d1 [NN_ * H_];
__device__ int   g_nidx[NN_ * KNN_];
__device__ float g_nval[NN_ * KNN_];
__device__ float g_bnscale[H_];
__device__ float g_bnshift[H_];
__device__ float g_gatec[NL_ * H_];
__device__ float g_sdebias[NSTEPS_ * H_];
__device__ float g_cv[(size_t)NN_ * NCAND];       // topk candidate values (23 MB)
__device__ int   g_ci[(size_t)NN_ * NCAND];       // topk candidate indices (23 MB)

// fp16 split copies of activations ([M,256] row-major hi/lo)
__device__ hf g_h_hi [NN_ * H_],  g_h_lo [NN_ * H_];
__device__ hf g_h2_hi[NN_ * H_],  g_h2_lo[NN_ * H_];
__device__ hf g_hn_hi[NN_ * H_],  g_hn_lo[NN_ * H_];
__device__ hf g_ag_hi[NN_ * H_],  g_ag_lo[NN_ * H_];

// transposed+split weights, [N,256] K-major; 9 slots of 64K elems
#define WSLOT 65536
__device__ hf g_w_hi[9 * WSLOT];
__device__ hf g_w_lo[9 * WSLOT];

// ================= helpers =================
__device__ __forceinline__ uint32_t smem_u32(const void* p) {
    uint32_t a;
    asm("{ .reg .u64 t; cvta.to.shared.u64 t, %1; cvt.u32.u64 %0, t; }" : "=r"(a) : "l"(p));
    return a;
}
__device__ __forceinline__ void ldsm4(uint32_t* r, uint32_t addr) {
    asm volatile("ldmatrix.sync.aligned.m8n8.x4.shared.b16 {%0,%1,%2,%3}, [%4];"
                 : "=r"(r[0]), "=r"(r[1]), "=r"(r[2]), "=r"(r[3]) : "r"(addr));
}
__device__ __forceinline__ void mma16816(float* d, const uint32_t* a, uint32_t b0, uint32_t b1) {
    asm volatile("mma.sync.aligned.m16n8k16.row.col.f32.f16.f16.f32 "
                 "{%0,%1,%2,%3}, {%4,%5,%6,%7}, {%8,%9}, {%0,%1,%2,%3};"
                 : "+f"(d[0]), "+f"(d[1]), "+f"(d[2]), "+f"(d[3])
                 : "r"(a[0]), "r"(a[1]), "r"(a[2]), "r"(a[3]), "r"(b0), "r"(b1));
}
__device__ __forceinline__ float fast_tanh(float x) {
    float ax = fabsf(x);
    float t = __expf(-2.f * ax);
    float r = __fdividef(1.f - t, 1.f + t);
    return copysignf(r, x);
}
__device__ __forceinline__ float fast_sigmoid(float x) {
    return __fdividef(1.f, 1.f + __expf(-x));
}
__device__ __forceinline__ void split2(float y0, float y1, hf* hi, hf* lo) {
    hf h0 = __float2half_rn(y0);
    hf h1 = __float2half_rn(y1);
    __half2 hp; hp.x = h0; hp.y = h1;
    __half2 lp;
    lp.x = __float2half_rn(y0 - __half2float(h0));
    lp.y = __float2half_rn(y1 - __half2float(h1));
    *(__half2*)hi = hp;
    *(__half2*)lo = lp;
}
#define CP_ASYNC16(sa, gp) \
    asm volatile("cp.async.cg.shared.global [%0], [%1], 16;" :: "r"(sa), "l"(gp))
#define CP_COMMIT() asm volatile("cp.async.commit_group;" ::: "memory")
#define CP_WAIT(n)  asm volatile("cp.async.wait_group %0;" :: "n"(n) : "memory")

#define TILE_B   8192                    // 128 rows * 32 hf * 2B
#define BUF_B    (4 * TILE_B)            // Ah,Al,Bh,Bl
#define MG_SMEM  (128 * 133 * 4)         // 68096 B: max(load bufs 64K, cand staging)

// tid-strided tile loader for NT threads (NT = 256 or 512)
template<int NT>
__device__ __forceinline__ void cpa_tile(const hf* __restrict__ src, int r0, int k0,
                                         char* __restrict__ dst, int tid)
{
#pragma unroll
    for (int u = 0; u < 512 / NT; u++) {
        int i = tid + u * NT;                // 512 16B segs
        int row = i >> 2;                    // 0..127
        int seg = i & 3;
        const void* gp = src + (size_t)(r0 + row) * 256 + k0 + seg * 8;
        uint32_t off = (uint32_t)row * 64u + (uint32_t)((seg ^ ((row >> 1) & 3)) << 4);
        CP_ASYNC16(smem_u32(dst + off), gp);
    }
}

// ================= dense tensor-core split-fp16 GEMM (512 thr, 32x32 warp tile) =================
__global__ __launch_bounds__(512) void mma_gemm(
    const hf* __restrict__ Ahi, const hf* __restrict__ Alo,
    const hf* __restrict__ Bhi, const hf* __restrict__ Blo,
    float* __restrict__ C, int Ntot, int ep,
    const float* __restrict__ p1, const float* __restrict__ p2,
    const float* __restrict__ p3, float alpha,
    hf* __restrict__ Chi, hf* __restrict__ Clo)
{
    const int bn0 = blockIdx.x * 128;
    const int bm0 = blockIdx.y * 128;

    extern __shared__ char smem[];
    char* bufp[2] = {smem, smem + BUF_B};

    const int tid  = threadIdx.x;
    const int wid  = tid >> 5;
    const int lane = tid & 31;
    const int warp_m = wid & 3;                 // rows  [warp_m*32, +32)
    const int warp_n = wid >> 2;                // cols  [warp_n*32, +32)

    float acc[2][4][4];
#pragma unroll
    for (int i = 0; i < 2; i++)
#pragma unroll
        for (int j = 0; j < 4; j++)
#pragma unroll
            for (int q = 0; q < 4; q++) acc[i][j][q] = 0.f;

    const int lrow  = lane & 15;
    const int lhalf = lane >> 4;

    cpa_tile<512>(Ahi, bm0, 0, bufp[0] + 0 * TILE_B, tid);
    cpa_tile<512>(Alo, bm0, 0, bufp[0] + 1 * TILE_B, tid);
    cpa_tile<512>(Bhi, bn0, 0, bufp[0] + 2 * TILE_B, tid);
    cpa_tile<512>(Blo, bn0, 0, bufp[0] + 3 * TILE_B, tid);
    CP_COMMIT();

    int buf = 0;
    for (int chunk = 0; chunk < 8; chunk++) {
        if (chunk + 1 < 8) {
            const int k1 = (chunk + 1) * 32;
            char* nb = bufp[buf ^ 1];
            cpa_tile<512>(Ahi, bm0, k1, nb + 0 * TILE_B, tid);
            cpa_tile<512>(Alo, bm0, k1, nb + 1 * TILE_B, tid);
            cpa_tile<512>(Bhi, bn0, k1, nb + 2 * TILE_B, tid);
            cpa_tile<512>(Blo, bn0, k1, nb + 3 * TILE_B, tid);
            CP_COMMIT();
            CP_WAIT(1);
        } else {
            CP_WAIT(0);
        }
        __syncthreads();

        const uint32_t sAh_b = smem_u32(bufp[buf] + 0 * TILE_B);
        const uint32_t sAl_b = smem_u32(bufp[buf] + 1 * TILE_B);
        const uint32_t sBh_b = smem_u32(bufp[buf] + 2 * TILE_B);
        const uint32_t sBl_b = smem_u32(bufp[buf] + 3 * TILE_B);

#pragma unroll
        for (int kk = 0; kk < 2; kk++) {
            const int segq = kk * 2 + lhalf;

            uint32_t aH[2][4], aL[2][4], bH[2][4], bL[2][4];
#pragma unroll
            for (int mt = 0; mt < 2; mt++) {
                int row = warp_m * 32 + mt * 16 + lrow;
                uint32_t off = (uint32_t)row * 64u + (uint32_t)((segq ^ ((row >> 1) & 3)) << 4);
                ldsm4(aH[mt], sAh_b + off);
                ldsm4(aL[mt], sAl_b + off);
            }
#pragma unroll
            for (int gg = 0; gg < 2; gg++) {
                int row = warp_n * 32 + gg * 16 + lrow;
                uint32_t off = (uint32_t)row * 64u + (uint32_t)((segq ^ ((row >> 1) & 3)) << 4);
                ldsm4(bH[gg], sBh_b + off);
                ldsm4(bL[gg], sBl_b + off);
            }

#define DO_TERM(Af, Bf)                                                        \
            _Pragma("unroll")                                                  \
            for (int mt = 0; mt < 2; mt++)                                     \
                _Pragma("unroll")                                              \
                for (int gg = 0; gg < 2; gg++) {                               \
                    mma16816(acc[mt][2 * gg + 0], Af[mt], Bf[gg][0], Bf[gg][2]); \
                    mma16816(acc[mt][2 * gg + 1], Af[mt], Bf[gg][1], Bf[gg][3]); \
                }
            DO_TERM(aH, bH)
            DO_TERM(aH, bL)
            DO_TERM(aL, bH)
#undef DO_TERM
        }
        __syncthreads();
        buf ^= 1;
    }

    auto epi = [&](float z, int gr, int gc) -> float {
        if (ep == 0) return z;
        if (ep == 1) return fmaxf(z + p1[gc], 0.f);
        if (ep == 2) return fmaxf(z + p1[gc], 0.f) * p2[gc] + p3[gc];
        if (ep == 3) return z + p1[gc];
        if (ep == 4) {
            float g = fast_sigmoid(z + p1[gc]);
            float a = p2[(size_t)gr * Ntot + gc];
            float hh = p3[(size_t)gr * Ntot + gc];
            return fmaxf(g * a + (1.f - g) * hh, 0.f);
        }
        if (ep == 5) return fast_tanh(z + p1[gc]);
        return p2[(size_t)gr * Ntot + gc] + fast_tanh(z + p1[gc]) * alpha;  // 6
    };

#pragma unroll
    for (int mt = 0; mt < 2; mt++) {
#pragma unroll
        for (int half = 0; half < 2; half++) {
            int gr = bm0 + warp_m * 32 + mt * 16 + (lane >> 2) + half * 8;
#pragma unroll
            for (int nt = 0; nt < 4; nt++) {
                int gc = bn0 + warp_n * 32 + nt * 8 + (lane & 3) * 2;
                float y0 = epi(acc[mt][nt][half * 2 + 0], gr, gc);
                float y1 = epi(acc[mt][nt][half * 2 + 1], gr, gc + 1);
                if (C) {
                    float2 o; o.x = y0; o.y = y1;
                    *(float2*)(C + (size_t)gr * Ntot + gc) = o;
                }
                if (Chi) {
                    split2(y0, y1, Chi + (size_t)gr * 256 + gc, Clo + (size_t)gr * 256 + gc);
                }
            }
        }
    }
}

// ================= sim GEMM + candidate extraction (256 thr, 32x64 warp tile) =================
__global__ __launch_bounds__(256, 2) void sim_cand(
    const hf* __restrict__ Ahi, const hf* __restrict__ Alo)
{
    const int bn0 = blockIdx.x * 128;
    const int bm0 = blockIdx.y * 128;
    if (bn0 > bm0) return;                      // symmetric: lower triangle only

    extern __shared__ char smem[];
    char* bufp[2] = {smem, smem + BUF_B};

    const int tid  = threadIdx.x;
    const int wid  = tid >> 5;
    const int lane = tid & 31;
    const int warp_m = wid & 3;                 // rows  [warp_m*32, +32)
    const int warp_n = wid >> 2;                // cols  [warp_n*64, +64)

    float acc[2][8][4];
#pragma unroll
    for (int i = 0; i < 2; i++)
#pragma unroll
        for (int j = 0; j < 8; j++)
#pragma unroll
            for (int q = 0; q < 4; q++) acc[i][j][q] = 0.f;

    const int lrow  = lane & 15;
    const int lhalf = lane >> 4;

    cpa_tile<256>(Ahi, bm0, 0, bufp[0] + 0 * TILE_B, tid);
    cpa_tile<256>(Alo, bm0, 0, bufp[0] + 1 * TILE_B, tid);
    cpa_tile<256>(Ahi, bn0, 0, bufp[0] + 2 * TILE_B, tid);
    cpa_tile<256>(Alo, bn0, 0, bufp[0] + 3 * TILE_B, tid);
    CP_COMMIT();

    int buf = 0;
    for (int chunk = 0; chunk < 8; chunk++) {
        if (chunk + 1 < 8) {
            const int k1 = (chunk + 1) * 32;
            char* nb = bufp[buf ^ 1];
            cpa_tile<256>(Ahi, bm0, k1, nb + 0 * TILE_B, tid);
            cpa_tile<256>(Alo, bm0, k1, nb + 1 * TILE_B, tid);
            cpa_tile<256>(Ahi, bn0, k1, nb + 2 * TILE_B, tid);
            cpa_tile<256>(Alo, bn0, k1, nb + 3 * TILE_B, tid);
            CP_COMMIT();
            CP_WAIT(1);
        } else {
            CP_WAIT(0);
        }
        __syncthreads();

        const uint32_t sAh_b = smem_u32(bufp[buf] + 0 * TILE_B);
        const uint32_t sAl_b = smem_u32(bufp[buf] + 1 * TILE_B);
        const uint32_t sBh_b = smem_u32(bufp[buf] + 2 * TILE_B);
        const uint32_t sBl_b = smem_u32(bufp[buf] + 3 * TILE_B);

#pragma unroll
        for (int kk = 0; kk < 2; kk++) {
            const int segq = kk * 2 + lhalf;

            uint32_t aH[2][4], aL[2][4], bH[4][4], bL[4][4];
#pragma unroll
            for (int mt = 0; mt < 2; mt++) {
                int row = warp_m * 32 + mt * 16 + lrow;
                uint32_t off = (uint32_t)row * 64u + (uint32_t)((segq ^ ((row >> 1) & 3)) << 4);
                ldsm4(aH[mt], sAh_b + off);
                ldsm4(aL[mt], sAl_b + off);
            }
#pragma unroll
            for (int gg = 0; gg < 4; gg++) {
                int row = warp_n * 64 + gg * 16 + lrow;
                uint32_t off = (uint32_t)row * 64u + (uint32_t)((segq ^ ((row >> 1) & 3)) << 4);
                ldsm4(bH[gg], sBh_b + off);
                ldsm4(bL[gg], sBl_b + off);
            }

#define DO_TERM(Af, Bf)                                                        \
            _Pragma("unroll")                                                  \
            for (int mt = 0; mt < 2; mt++)                                     \
                _Pragma("unroll")                                              \
                for (int gg = 0; gg < 4; gg++) {                               \
                    mma16816(acc[mt][2 * gg + 0], Af[mt], Bf[gg][0], Bf[gg][2]); \
                    mma16816(acc[mt][2 * gg + 1], Af[mt], Bf[gg][1], Bf[gg][3]); \
                }
            DO_TERM(aH, bH)
            DO_TERM(aH, bL)
            DO_TERM(aL, bH)
#undef DO_TERM
        }
        __syncthreads();
        buf ^= 1;
    }

    // ---- stage full 128x128 tile, pitch 133 (conflict-free row & col scans) ----
    float* ts = (float*)smem;
#pragma unroll
    for (int mt = 0; mt < 2; mt++)
#pragma unroll
        for (int half = 0; half < 2; half++) {
            int lr = warp_m * 32 + mt * 16 + (lane >> 2) + half * 8;
#pragma unroll
            for (int nt = 0; nt < 8; nt++) {
                int lc = warp_n * 64 + nt * 8 + (lane & 3) * 2;
                ts[lr * 133 + lc]     = acc[mt][nt][half * 2 + 0];
                ts[lr * 133 + lc + 1] = acc[mt][nt][half * 2 + 1];
            }
        }
    __syncthreads();

    float lv[KNN_]; int li[KNN_];
    if (tid < 128) {
        // direct: row bm0+tid, cols bn0..+127
        int r = tid;
#pragma unroll
        for (int q = 0; q < KNN_; q++) { lv[q] = -INFINITY; li[q] = 0x7fffffff; }
        for (int c = 0; c < 128; c++) {
            float v = ts[r * 133 + c];
            if (v > lv[KNN_ - 1]) {
                int p = KNN_ - 1;
                while (p > 0 && v > lv[p - 1]) { lv[p] = lv[p - 1]; li[p] = li[p - 1]; p--; }
                lv[p] = v; li[p] = bn0 + c;
            }
        }
        size_t base = (size_t)(bm0 + r) * NCAND + (size_t)(bn0 >> 7) * KNN_;
#pragma unroll
        for (int q = 0; q < KNN_; q++) { g_cv[base + q] = lv[q]; g_ci[base + q] = li[q]; }
    } else if (bm0 != bn0) {
        // mirror: row bn0+c, cols bm0..+127 (column scan of staged tile)
        int c = tid - 128;
#pragma unroll
        for (int q = 0; q < KNN_; q++) { lv[q] = -INFINITY; li[q] = 0x7fffffff; }
        for (int r = 0; r < 128; r++) {
            float v = ts[r * 133 + c];
            if (v > lv[KNN_ - 1]) {
                int p = KNN_ - 1;
                while (p > 0 && v > lv[p - 1]) { lv[p] = lv[p - 1]; li[p] = li[p - 1]; p--; }
                lv[p] = v; li[p] = bm0 + r;
            }
        }
        size_t base = (size_t)(bn0 + c) * NCAND + (size_t)(bm0 >> 7) * KNN_;
#pragma unroll
        for (int q = 0; q < KNN_; q++) { g_cv[base + q] = lv[q]; g_ci[base + q] = li[q]; }
    }
}

// ================= fused persistent SDE kernel (256 thr / 32 rows / 2 CTAs per SM) =================
// 10 steps x 3 layers; 256 CTAs x 32 rows. Warp tile 16x64 (2x4 warp grid).
// h in registers; u splits in smem; weights double-buffered 32-k ring; next-layer
// chunk-0 prefetch issued BEFORE the epilogue so its latency hides under tanh/stores.
#define SDE_UH   0                       // hf, swizzled    16 KB (32 rows)
#define SDE_UL   16384                   // hf, swizzled    16 KB
#define SDE_W    32768                   // ring: 2 x (hi16K + lo16K) = 64 KB
#define SDE_SMEM 98304

__device__ __forceinline__ void sde_wchunk(const hf* __restrict__ W, int k0,
                                           char* __restrict__ dst, int tid)
{
#pragma unroll
    for (int u = 0; u < 4; u++) {
        int i = tid + u * 256;               // 1024 segs: 256 rows x 4
        int row = i >> 2, seg = i & 3;
        const void* gp = W + (size_t)row * 256 + k0 + seg * 8;
        uint32_t off = (uint32_t)row * 64u + (uint32_t)((seg ^ ((row >> 1) & 3)) << 4);
        CP_ASYNC16(smem_u32(dst + off), gp);
    }
}

__global__ __launch_bounds__(256, 2) void sde_fused(
    const hf* __restrict__ W1h, const hf* __restrict__ W1l,
    const hf* __restrict__ W2h, const hf* __restrict__ W2l,
    const hf* __restrict__ W3h, const hf* __restrict__ W3l,
    const float* __restrict__ sdeb, const float* __restrict__ b2,
    const float* __restrict__ b3,
    const float* __restrict__ hin,
    hf* __restrict__ hhi_g, hf* __restrict__ hlo_g)
{
    extern __shared__ char smem[];
    char* sUh = smem + SDE_UH;
    char* sUl = smem + SDE_UL;
    char* sW  = smem + SDE_W;

    const int tid  = threadIdx.x;
    const int wid  = tid >> 5;
    const int lane = tid & 31;
    const int warp_m = wid & 1;              // 2 warps over m (16 rows each)
    const int warp_n = wid >> 1;             // 4 warps over n (64 cols each)
    const int r0 = blockIdx.x * 32;
    const int lrow  = lane & 15;
    const int lhalf = lane >> 4;

    // u-split initial load (swizzled chunk layout; chunk stride 2048 B)
#pragma unroll
    for (int u = 0; u < 4; u++) {
        int i = tid + u * 256;               // 1024 segs: 32 rows x 32
        int row = i >> 5, s32 = i & 31;
        int chunk = s32 >> 2, seg = s32 & 3;
        uint32_t off = (uint32_t)chunk * 2048u + (uint32_t)row * 64u
                     + (uint32_t)((seg ^ ((row >> 1) & 3)) << 4);
        CP_ASYNC16(smem_u32(sUh + off), (const void*)(hhi_g + (size_t)(r0 + row) * 256 + s32 * 8));
        CP_ASYNC16(smem_u32(sUl + off), (const void*)(hlo_g + (size_t)(r0 + row) * 256 + s32 * 8));
    }
    CP_COMMIT();

    // h state into registers (exactly the elements this thread's epilogue owns)
    float hreg[2][8][2];
#pragma unroll
    for (int half = 0; half < 2; half++) {
        int lr = warp_m * 16 + (lane >> 2) + half * 8;
#pragma unroll
        for (int nt = 0; nt < 8; nt++) {
            int gc = warp_n * 64 + nt * 8 + (lane & 3) * 2;
            float2 v = *(const float2*)(hin + (size_t)(r0 + lr) * 256 + gc);
            hreg[half][nt][0] = v.x;
            hreg[half][nt][1] = v.y;
        }
    }

    const hf* Whs[3] = {W1h, W2h, W3h};
    const hf* Wls[3] = {W1l, W2l, W3l};

    // prefetch layer-0 chunk 0 into ring buf 0
    sde_wchunk(W1h, 0, sW, tid);
    sde_wchunk(W1l, 0, sW + 16384, tid);
    CP_COMMIT();
    CP_WAIT(1);                               // u-splits done; chunk0 in flight
    __syncthreads();

#pragma unroll 1
    for (int inst = 0; inst < 3 * NSTEPS_; inst++) {
        const int layer = inst % 3;
        const int step  = inst / 3;
        const float* bias = (layer == 0) ? (sdeb + step * H_) : (layer == 1) ? b2 : b3;
        const hf* Wh = Whs[layer];
        const hf* Wl = Wls[layer];

        float acc[8][4];
#pragma unroll
        for (int j = 0; j < 8; j++)
#pragma unroll
            for (int q = 0; q < 4; q++) acc[j][q] = 0.f;

        int wb = 0;
#pragma unroll 1
        for (int kc = 0; kc < 8; kc++) {
            if (kc + 1 < 8) {
                char* nb = sW + (wb ^ 1) * 32768;
                sde_wchunk(Wh, (kc + 1) * 32, nb, tid);
                sde_wchunk(Wl, (kc + 1) * 32, nb + 16384, tid);
                CP_COMMIT();
                CP_WAIT(1);
            } else {
                CP_WAIT(0);
            }
            __syncthreads();

            const uint32_t sWh_b = smem_u32(sW + wb * 32768);
            const uint32_t sWl_b = sWh_b + 16384;
            const uint32_t sAh_b = smem_u32(sUh) + (uint32_t)kc * 2048u;
            const uint32_t sAl_b = smem_u32(sUl) + (uint32_t)kc * 2048u;

#pragma unroll
            for (int kk = 0; kk < 2; kk++) {
                const int segq = kk * 2 + lhalf;
                uint32_t aH[4], aL[4], bH[4][4], bL[4][4];
                {
                    int row = warp_m * 16 + lrow;
                    uint32_t off = (uint32_t)row * 64u
                                 + (uint32_t)((segq ^ ((row >> 1) & 3)) << 4);
                    ldsm4(aH, sAh_b + off);
                    ldsm4(aL, sAl_b + off);
                }
#pragma unroll
                for (int gg = 0; gg < 4; gg++) {
                    int row = warp_n * 64 + gg * 16 + lrow;
                    uint32_t off = (uint32_t)row * 64u
                                 + (uint32_t)((segq ^ ((row >> 1) & 3)) << 4);
                    ldsm4(bH[gg], sWh_b + off);
                    ldsm4(bL[gg], sWl_b + off);
                }
#define DO_TERM4(Af, Bf)                                                       \
                _Pragma("unroll")                                              \
                for (int gg = 0; gg < 4; gg++) {                               \
                    mma16816(acc[2 * gg + 0], Af, Bf[gg][0], Bf[gg][2]);       \
                    mma16816(acc[2 * gg + 1], Af, Bf[gg][1], Bf[gg][3]);       \
                }
                DO_TERM4(aH, bH)
                DO_TERM4(aH, bL)
                DO_TERM4(aL, bH)
#undef DO_TERM4
            }
            __syncthreads();
            wb ^= 1;
        }

        // prefetch NEXT layer's chunk 0 before the epilogue (overlaps fetch with tanh/stores)
        if (inst + 1 < 3 * NSTEPS_) {
            const int nl = (inst + 1) % 3;
            char* nb = sW + wb * 32768;          // wb == 0 after 8 toggles
            sde_wchunk(Whs[nl], 0, nb, tid);
            sde_wchunk(Wls[nl], 0, nb + 16384, tid);
            CP_COMMIT();
        }

        const bool lastL = (layer == 2);
        const bool fin = lastL && (step == NSTEPS_ - 1);
#pragma unroll
        for (int half = 0; half < 2; half++) {
            int lr = warp_m * 16 + (lane >> 2) + half * 8;
#pragma unroll
            for (int nt = 0; nt < 8; nt++) {
                int gc = warp_n * 64 + nt * 8 + (lane & 3) * 2;
                float y0 = fast_tanh(acc[nt][half * 2 + 0] + bias[gc]);
                float y1 = fast_tanh(acc[nt][half * 2 + 1] + bias[gc + 1]);
                if (lastL) {
                    y0 = hreg[half][nt][0] + y0 * 0.1f;
                    y1 = hreg[half][nt][1] + y1 * 0.1f;
                    if (!fin) {
                        hreg[half][nt][0] = y0;
                        hreg[half][nt][1] = y1;
                    }
                }
                if (fin) {
                    split2(y0, y1, hhi_g + (size_t)(r0 + lr) * 256 + gc,
                                   hlo_g + (size_t)(r0 + lr) * 256 + gc);
                } else {
                    int chunk = gc >> 5, k = gc & 31, seg = k >> 3;
                    uint32_t boff = (uint32_t)chunk * 2048u + (uint32_t)lr * 64u
                                  + (uint32_t)((seg ^ ((lr >> 1) & 3)) << 4)
                                  + (uint32_t)(k & 7) * 2u;
                    split2(y0, y1, (hf*)(sUh + boff), (hf*)(sUl + boff));
                }
            }
        }
        __syncthreads();
    }
}

// ================= SIMT fp32 GEMM (odd shapes: enc1 K=83, dec2 N=34) =================
#define BM 128
#define BN 128
#define BK 8

__global__ __launch_bounds__(256) void gemm_kernel(
    const float* __restrict__ A, const float* __restrict__ B, float* __restrict__ C,
    int M, int N, int K, int ldb, int ep,
    const float* __restrict__ p1, hf* __restrict__ Chi, hf* __restrict__ Clo)
{
    __shared__ float As[2][BK][BM + 4];
    __shared__ float Bs[2][BK][BN + 4];

    const int tid = threadIdx.x;
    const int tx  = tid & 15;
    const int ty  = tid >> 4;
    const int bn0 = blockIdx.x * BN;
    const int bm0 = blockIdx.y * BM;

    float acc[8][8];
#pragma unroll
    for (int i = 0; i < 8; i++)
#pragma unroll
        for (int j = 0; j < 8; j++) acc[i][j] = 0.f;

    const int aRow = tid >> 1;
    const int aK   = (tid & 1) * 4;
    const int bRow = tid >> 5;
    const int bN   = (tid & 31) * 4;

    float ra[4], rb[4];
    const int ktiles = (K + BK - 1) / BK;

#define LOAD_AB(kt) do {                                                       \
        int k0_ = (kt) * BK;                                                   \
        int gr_ = bm0 + aRow, gk_ = k0_ + aK;                                  \
        _Pragma("unroll")                                                      \
        for (int j_ = 0; j_ < 4; j_++)                                         \
            ra[j_] = (gr_ < M && gk_ + j_ < K) ? A[(size_t)gr_ * K + gk_ + j_] : 0.f; \
        int gk2_ = k0_ + bRow, gn_ = bn0 + bN;                                 \
        _Pragma("unroll")                                                      \
        for (int j_ = 0; j_ < 4; j_++)                                         \
            rb[j_] = (gk2_ < K && gn_ + j_ < N) ? B[(size_t)gk2_ * ldb + gn_ + j_] : 0.f; \
    } while (0)

#define STS_AB2(buf) do {                                                      \
        _Pragma("unroll")                                                      \
        for (int j_ = 0; j_ < 4; j_++) As[buf][aK + j_][aRow] = ra[j_];        \
        _Pragma("unroll")                                                      \
        for (int j_ = 0; j_ < 4; j_++) Bs[buf][bRow][bN + j_] = rb[j_];        \
    } while (0)

    LOAD_AB(0);
    STS_AB2(0);
    __syncthreads();

    int cur = 0;
    for (int kt = 0; kt < ktiles; kt++) {
        const int hasNext = (kt + 1 < ktiles);
        if (hasNext) LOAD_AB(kt + 1);
#pragma unroll
        for (int kk = 0; kk < BK; kk++) {
            const float* as = As[cur][kk];
            const float* bs = Bs[cur][kk];
            float4 A0 = *(const float4*)(as + ty * 4);
            float4 A1 = *(const float4*)(as + 64 + ty * 4);
            float4 B0 = *(const float4*)(bs + tx * 4);
            float4 B1 = *(const float4*)(bs + 64 + tx * 4);
            float av[8] = {A0.x, A0.y, A0.z, A0.w, A1.x, A1.y, A1.z, A1.w};
            float bv[8] = {B0.x, B0.y, B0.z, B0.w, B1.x, B1.y, B1.z, B1.w};
#pragma unroll
            for (int i = 0; i < 8; i++)
#pragma unroll
                for (int j = 0; j < 8; j++)
                    acc[i][j] = fmaf(av[i], bv[j], acc[i][j]);
        }
        if (hasNext) { STS_AB2(cur ^ 1); __syncthreads(); cur ^= 1; }
    }

#pragma unroll
    for (int i = 0; i < 8; i++) {
        int gr = bm0 + ((i < 4) ? (ty * 4 + i) : (64 + ty * 4 + (i - 4)));
        if (gr >= M) continue;
#pragma unroll
        for (int j = 0; j < 8; j++) {
            int gc = bn0 + ((j < 4) ? (tx * 4 + j) : (64 + tx * 4 + (j - 4)));
            if (gc >= N) continue;
            float z = acc[i][j];
            float y;
            if (ep == 1) y = fmaxf(z + p1[gc], 0.f);
            else if (ep == 3) y = z + p1[gc];
            else y = z;
            if (C) C[(size_t)gr * N + gc] = y;
            if (Chi) {
                hf hb = __float2half_rn(y);
                Chi[(size_t)gr * 256 + gc] = hb;
                Clo[(size_t)gr * 256 + gc] = __float2half_rn(y - __half2float(hb));
            }
        }
    }
}

// ---------------- row-normalize h -> hn splits (fp32 hn is dead; only splits used) ----------------
__global__ void rownorm_kernel()
{
    int row = blockIdx.x;
    int tid = threadIdx.x;                   // 256 == H_
    float v = g_h[row * H_ + tid];
    float s = v * v;
#pragma unroll
    for (int o = 16; o > 0; o >>= 1) s += __shfl_xor_sync(0xffffffff, s, o);
    __shared__ float ws[8];
    if ((tid & 31) == 0) ws[tid >> 5] = s;
    __syncthreads();
    if (tid < 8) {
        float t = ws[tid];
#pragma unroll
        for (int o = 4; o > 0; o >>= 1) t += __shfl_xor_sync(0xff, t, o);
        if (tid == 0) ws[0] = t;
    }
    __syncthreads();
    float denom = fmaxf(sqrtf(ws[0]), 1e-12f);
    float y = v / denom;
    hf hb = __float2half_rn(y);
    g_hn_hi[row * H_ + tid] = hb;
    g_hn_lo[row * H_ + tid] = __float2half_rn(y - __half2float(hb));
}

// ---------------- top-k over per-tile candidates + adjacency normalize ----------------
__global__ void topk_kernel()
{
    const int row = blockIdx.x;
    const int tid = threadIdx.x;             // 256
    const float* cv = g_cv + (size_t)row * NCAND;
    const int*   ci = g_ci + (size_t)row * NCAND;

    float lv[KNN_];
    int   li[KNN_];
#pragma unroll
    for (int r = 0; r < KNN_; r++) { lv[r] = -INFINITY; li[r] = 0x7fffffff; }

    for (int j = tid; j < NCAND; j += 256) {
        float v = cv[j];
        int ii = ci[j];
        if (v > lv[KNN_ - 1] || (v == lv[KNN_ - 1] && ii < li[KNN_ - 1])) {
            int p = KNN_ - 1;
            while (p > 0 && (v > lv[p - 1] || (v == lv[p - 1] && ii < li[p - 1]))) {
                lv[p] = lv[p - 1]; li[p] = li[p - 1]; p--;
            }
            lv[p] = v; li[p] = ii;
        }
    }

    __shared__ float sv[256 * KNN_];
    __shared__ int   si[256 * KNN_];
#pragma unroll
    for (int r = 0; r < KNN_; r++) { sv[tid * KNN_ + r] = lv[r]; si[tid * KNN_ + r] = li[r]; }
    __syncthreads();

    __shared__ float rv[256];
    __shared__ int   ri[256];
    __shared__ int   rp[256];
    __shared__ float outv[KNN_];
    __shared__ int   outi[KNN_];

    const int TOT = 256 * KNN_;
    for (int r = 0; r < KNN_; r++) {
        float bv = -INFINITY; int bi = 0x7fffffff; int bp = -1;
        for (int t = tid; t < TOT; t += 256) {
            float v = sv[t]; int ii = si[t];
            if (v > bv || (v == bv && ii < bi)) { bv = v; bi = ii; bp = t; }
        }
        rv[tid] = bv; ri[tid] = bi; rp[tid] = bp;
        __syncthreads();
        for (int s = 128; s > 0; s >>= 1) {
            if (tid < s) {
                float v2 = rv[tid + s]; int i2 = ri[tid + s];
                if (v2 > rv[tid] || (v2 == rv[tid] && i2 < ri[tid])) {
                    rv[tid] = v2; ri[tid] = i2; rp[tid] = rp[tid + s];
                }
            }
            __syncthreads();
        }
        if (tid == 0) {
            outv[r] = rv[0]; outi[r] = ri[0];
            sv[rp[0]] = -INFINITY;
            si[rp[0]] = 0x7fffffff;
        }
        __syncthreads();
    }

    if (tid == 0) {
        float s = 0.f;
#pragma unroll
        for (int r = 0; r < KNN_; r++) s += outv[r];
        float inv = 1.f / fmaxf(s, 1.f);
#pragma unroll
        for (int r = 0; r < KNN_; r++) {
            g_nidx[row * KNN_ + r] = outi[r];
            g_nval[row * KNN_ + r] = outv[r] * inv;
        }
    }
}

// ---------------- sparse aggregation (+ fp16 split) ----------------
__global__ void agg_kernel()
{
    int row = blockIdx.x;
    int tid = threadIdx.x;                  // 256 == H_
    float acc = 0.f;
#pragma unroll
    for (int r = 0; r < KNN_; r++) {
        float w = g_nval[row * KNN_ + r];
        int   n = g_nidx[row * KNN_ + r];
        acc += w * g_h2[(size_t)n * H_ + tid];
    }
    g_agg[row * H_ + tid] = acc;
    hf hb = __float2half_rn(acc);
    g_ag_hi[row * H_ + tid] = hb;
    g_ag_lo[row * H_ + tid] = __float2half_rn(acc - __half2float(hb));
}

// ---------------- all weight transposes+splits in ONE launch ----------------
__global__ void wsplit_all(
    const float* w0, const float* w1, const float* w2, const float* w3,
    const float* w4, const float* w5, const float* w6, const float* w7,
    const float* w8, hf* __restrict__ hi_base, hf* __restrict__ lo_base)
{
    const int slot = blockIdx.z;
    const float* W = (slot == 0) ? w0 : (slot == 1) ? w1 : (slot == 2) ? w2 :
                     (slot == 3) ? w3 : (slot == 4) ? w4 : (slot == 5) ? w5 :
                     (slot == 6) ? w6 : (slot == 7) ? w7 : w8;
    const int N = (slot == 8) ? 128 : 256;
    hf* hi = hi_base + (size_t)slot * WSLOT;
    hf* lo = lo_base + (size_t)slot * WSLOT;

    __shared__ float t[32][33];
    const int n0 = blockIdx.x * 32;
    if (n0 >= N) return;
    const int k0 = blockIdx.y * 32;
    const int tx = threadIdx.x;
    const int ty = threadIdx.y;
#pragma unroll
    for (int i = ty; i < 32; i += 8)
        t[i][tx] = W[(size_t)(k0 + i) * N + n0 + tx];
    __syncthreads();
#pragma unroll
    for (int i = ty; i < 32; i += 8) {
        float v = t[tx][i];
        hf hb = __float2half_rn(v);
        hi[(size_t)(n0 + i) * 256 + k0 + tx] = hb;
        lo[(size_t)(n0 + i) * 256 + k0 + tx] = __float2half_rn(v - __half2float(hb));
    }
}

// ---------------- tiny precompute ----------------
__global__ void precompute_kernel(const float* __restrict__ bn_g, const float* __restrict__ bn_b,
                                  const float* __restrict__ bn_m, const float* __restrict__ bn_v,
                                  const float* __restrict__ t_w1, const float* __restrict__ t_b1,
                                  const float* __restrict__ t_w2, const float* __restrict__ t_b2,
                                  const float* __restrict__ gate_w, const float* __restrict__ gate_b,
                                  const float* __restrict__ sde_w1, const float* __restrict__ sde_b1)
{
    int b = blockIdx.x;
    int j = threadIdx.x;
    if (b == 0) {
        float s = bn_g[j] * rsqrtf(bn_v[j] + 1e-5f);
        g_bnscale[j] = s;
        g_bnshift[j] = bn_b[j] - bn_m[j] * s;
    } else if (b <= NL_) {
        int l = b - 1;
        float t = 0.5f * (float)l;
        __shared__ float te[TD_];
        __shared__ float te2[H_];
        if (j < TD_) te[j] = fmaxf(t * t_w1[l * TD_ + j] + t_b1[l * TD_ + j], 0.f);
        __syncthreads();
        float acc = t_b2[l * H_ + j];
#pragma unroll
        for (int k = 0; k < TD_; k++) acc += te[k] * t_w2[l * TD_ * H_ + k * H_ + j];
        te2[j] = acc;
        __syncthreads();
        float c = gate_b[l * H_ + j];
        const float* W = gate_w + (size_t)l * 2 * H_ * H_ + (size_t)H_ * H_;
        for (int k = 0; k < H_; k++) c += te2[k] * W[k * H_ + j];
        g_gatec[l * H_ + j] = c;
    } else {
        int s = b - 1 - NL_;
        float ts = (float)s * 0.1f;
        g_sdebias[s * H_ + j] = sde_b1[j] + ts * sde_w1[H_ * H_ + j];
    }
}

// ---------------- host ----------------
static inline void launch_mma(const hf* Ahi, const hf* Alo, const hf* Bhi, const hf* Blo,
                              float* C, int Ntot, int ep,
                              const float* p1 = nullptr, const float* p2 = nullptr,
                              const float* p3 = nullptr, float alpha = 0.f,
                              hf* Chi = nullptr, hf* Clo = nullptr)
{
    dim3 grid(Ntot / 128, NN_ / 128);
    mma_gemm<<<grid, 512, MG_SMEM>>>(Ahi, Alo, Bhi, Blo, C, Ntot, ep,
                                     p1, p2, p3, alpha, Chi, Clo);
}

extern "C" void kernel_launch(void* const* d_in, const int* in_sizes, int n_in,
                              void* d_out, int out_size)
{
    const float* x       = (const float*)d_in[0];
    const float* enc_w1  = (const float*)d_in[1];
    const float* enc_b1  = (const float*)d_in[2];
    const float* enc_w2  = (const float*)d_in[3];
    const float* enc_b2  = (const float*)d_in[4];
    const float* bn_g    = (const float*)d_in[5];
    const float* bn_b    = (const float*)d_in[6];
    const float* bn_m    = (const float*)d_in[7];
    const float* bn_v    = (const float*)d_in[8];
    const float* node_w  = (const float*)d_in[9];
    const float* node_b  = (const float*)d_in[10];
    const float* t_w1    = (const float*)d_in[11];
    const float* t_b1    = (const float*)d_in[12];
    const float* t_w2    = (const float*)d_in[13];
    const float* t_b2    = (const float*)d_in[14];
    const float* gate_w  = (const float*)d_in[15];
    const float* gate_b  = (const float*)d_in[16];
    const float* sde_w1  = (const float*)d_in[17];
    const float* sde_b1  = (const float*)d_in[18];
    const float* sde_w2  = (const float*)d_in[19];
    const float* sde_b2  = (const float*)d_in[20];
    const float* sde_w3  = (const float*)d_in[21];
    const float* sde_b3  = (const float*)d_in[22];
    const float* dec_w1  = (const float*)d_in[23];
    const float* dec_b1  = (const float*)d_in[24];
    const float* dec_w2  = (const float*)d_in[25];
    const float* dec_b2  = (const float*)d_in[26];
    float* out = (float*)d_out;

    cudaFuncSetAttribute(mma_gemm, cudaFuncAttributeMaxDynamicSharedMemorySize, MG_SMEM);
    cudaFuncSetAttribute(sim_cand, cudaFuncAttributeMaxDynamicSharedMemorySize, MG_SMEM);
    cudaFuncSetAttribute(sde_fused, cudaFuncAttributeMaxDynamicSharedMemorySize, SDE_SMEM);

    float *h, *h2, *agg, *d1, *bns, *bnsh, *gatec, *sdeb;
    hf *hhi, *hlo, *h2hi, *h2lo, *hnhi, *hnlo, *aghi, *aglo, *whi, *wlo;
    cudaGetSymbolAddress((void**)&h,     g_h);
    cudaGetSymbolAddress((void**)&h2,    g_h2);
    cudaGetSymbolAddress((void**)&agg,   g_agg);
    cudaGetSymbolAddress((void**)&d1,    g_d1);
    cudaGetSymbolAddress((void**)&bns,   g_bnscale);
    cudaGetSymbolAddress((void**)&bnsh,  g_bnshift);
    cudaGetSymbolAddress((void**)&gatec, g_gatec);
    cudaGetSymbolAddress((void**)&sdeb,  g_sdebias);
    cudaGetSymbolAddress((void**)&hhi,  g_h_hi);  cudaGetSymbolAddress((void**)&hlo,  g_h_lo);
    cudaGetSymbolAddress((void**)&h2hi, g_h2_hi); cudaGetSymbolAddress((void**)&h2lo, g_h2_lo);
    cudaGetSymbolAddress((void**)&hnhi, g_hn_hi); cudaGetSymbolAddress((void**)&hnlo, g_hn_lo);
    cudaGetSymbolAddress((void**)&aghi, g_ag_hi); cudaGetSymbolAddress((void**)&aglo, g_ag_lo);
    cudaGetSymbolAddress((void**)&whi, g_w_hi);   cudaGetSymbolAddress((void**)&wlo, g_w_lo);

    // (1) precompute
    precompute_kernel<<<1 + NL_ + NSTEPS_, 256>>>(bn_g, bn_b, bn_m, bn_v,
                                                  t_w1, t_b1, t_w2, t_b2,
                                                  gate_w, gate_b, sde_w1, sde_b1);
    // (2) ALL weight splits in one launch
    {
        dim3 grid(8, 8, 9);
        wsplit_all<<<grid, dim3(32, 8)>>>(
            enc_w2, node_w, node_w + H_ * H_, gate_w, gate_w + 2 * H_ * H_,
            sde_w1, sde_w2, sde_w3, dec_w1, whi, wlo);
    }
    // (3) enc1 SIMT (K=83), splits only
    {
        dim3 grid((H_ + BN - 1) / BN, (NN_ + BM - 1) / BM);
        gemm_kernel<<<grid, 256>>>(x, enc_w1, nullptr, NN_, H_, DIN_, H_, 1, enc_b1, h2hi, h2lo);
    }
    // (4) enc2 mma (dense, 512-thr config)
    launch_mma(h2hi, h2lo, whi + 0 * WSLOT, wlo + 0 * WSLOT, h, 256, /*ep=*/2,
               enc_b2, bns, bnsh, 0.f, hhi, hlo);
    // (5) rownorm
    rownorm_kernel<<<NN_, 256>>>();
    // (6) sim GEMM + fused candidate extraction (256-thr 2-CTA config)
    {
        dim3 grid(NN_ / 128, NN_ / 128);
        sim_cand<<<grid, 256, MG_SMEM>>>(hnhi, hnlo);
    }
    // (7) top-k over candidates
    topk_kernel<<<NN_, 256>>>();

    // temporal gated graph conv layers
    for (int l = 0; l < NL_; l++) {
        launch_mma(hhi, hlo, whi + (1 + l) * WSLOT, wlo + (1 + l) * WSLOT, h2, 256, /*ep=*/3,
                   node_b + (size_t)l * H_);
        agg_kernel<<<NN_, 256>>>();
        launch_mma(aghi, aglo, whi + (3 + l) * WSLOT, wlo + (3 + l) * WSLOT, h, 256, /*ep=*/4,
                   gatec + (size_t)l * H_, agg, h2, 0.f, hhi, hlo);
    }

    // SDE: fused persistent kernel (256 CTAs x 32 rows, 2 CTAs/SM, h in regs)
    sde_fused<<<NN_ / 32, 256, SDE_SMEM>>>(
        whi + 5 * WSLOT, wlo + 5 * WSLOT,
        whi + 6 * WSLOT, wlo + 6 * WSLOT,
        whi + 7 * WSLOT, wlo + 7 * WSLOT,
        sdeb, sde_b2, sde_b3, h, hhi, hlo);

    // decoder: dec1 tensor (N=128), dec2 SIMT (K=128, N=34)
    launch_mma(hhi, hlo, whi + 8 * WSLOT, wlo + 8 * WSLOT, d1, 128, /*ep=*/1, dec_b1);
    {
        dim3 grid((C_ + BN - 1) / BN, (NN_ + BM - 1) / BM);
        gemm_kernel<<<grid, 256>>>(d1, dec_w2, out, NN_, C_, H_ / 2, C_, 3, dec_b2, nullptr, nullptr);
    }
}